// round 14
// baseline (speedup 1.0000x reference)
#include <cuda_runtime.h>
#include <cuda_fp16.h>
#include <cstdint>
#include <cstddef>

typedef unsigned short ushort_t;

#define NTOK 8192
#define EEXP 16
#define CAPS 640
#define RBLKS (NTOK/8)

// ---------------- static device scratch ----------------
__device__ ushort_t g_xh[(size_t)NTOK * 1024];
__device__ ushort_t g_hh[(size_t)EEXP * CAPS * 4096];
__device__ float g_gate[NTOK];
__device__ int   g_cnt[EEXP];
__device__ int   g_lst_tok[EEXP * NTOK];
__device__ float g_lst_gate[EEXP * NTOK];
__device__ int   g_tok4slot[EEXP * CAPS];
__device__ float g_slotgate[EEXP * CAPS];
__device__ float g_pp[RBLKS * 16];
__device__ int   g_pf[RBLKS * 16];
__device__ float g_pz[RBLKS];
__device__ int   g_pn[RBLKS];

// ---------------- helpers ----------------
__device__ __forceinline__ uint32_t f2h(float f) {
    return (uint32_t)__half_as_ushort(__float2half_rn(f));
}
__device__ __forceinline__ uint32_t smem_u32(const void* p) {
    uint32_t a;
    asm("{ .reg .u64 t; cvta.to.shared.u64 t, %1; cvt.u32.u64 %0, t; }" : "=r"(a) : "l"(p));
    return a;
}
__device__ __forceinline__ void cpa16(uint32_t d, const void* s) {
    asm volatile("cp.async.cg.shared.global [%0], [%1], 16;" :: "r"(d), "l"(s));
}
__device__ __forceinline__ void cp_commit() { asm volatile("cp.async.commit_group;"); }
__device__ __forceinline__ void cp_wait0() { asm volatile("cp.async.wait_group 0;" ::: "memory"); }
__device__ __forceinline__ void ldsm4(uint32_t* r, uint32_t a) {
    asm volatile("ldmatrix.sync.aligned.m8n8.x4.shared.b16 {%0,%1,%2,%3}, [%4];"
        : "=r"(r[0]), "=r"(r[1]), "=r"(r[2]), "=r"(r[3]) : "r"(a));
}
__device__ __forceinline__ void ldsm4t(uint32_t* r, uint32_t a) {
    asm volatile("ldmatrix.sync.aligned.m8n8.x4.trans.shared.b16 {%0,%1,%2,%3}, [%4];"
        : "=r"(r[0]), "=r"(r[1]), "=r"(r[2]), "=r"(r[3]) : "r"(a));
}
__device__ __forceinline__ void mmaf16(float* c, const uint32_t* a, uint32_t b0, uint32_t b1) {
    asm volatile("mma.sync.aligned.m16n8k16.row.col.f32.f16.f16.f32 "
        "{%0,%1,%2,%3}, {%4,%5,%6,%7}, {%8,%9}, {%0,%1,%2,%3};"
        : "+f"(c[0]), "+f"(c[1]), "+f"(c[2]), "+f"(c[3])
        : "r"(a[0]), "r"(a[1]), "r"(a[2]), "r"(a[3]), "r"(b0), "r"(b1));
}

// ---------------- init: zero y + expert counters ----------------
__global__ void init_kernel(float* __restrict__ out, long ytot) {
    if (blockIdx.x == 0 && threadIdx.x < EEXP) g_cnt[threadIdx.x] = 0;
    long i4 = (long)blockIdx.x * blockDim.x + threadIdx.x;
    long n4 = ytot >> 2;
    long stride = (long)gridDim.x * blockDim.x;
    float4 z = make_float4(0.f, 0.f, 0.f, 0.f);
    for (; i4 < n4; i4 += stride) reinterpret_cast<float4*>(out)[i4] = z;
}

// ---------------- fp16 pack (x only) ----------------
__global__ void pack_kernel(const float* __restrict__ in, ushort_t* __restrict__ h, long n4)
{
    long i = (long)blockIdx.x * blockDim.x + threadIdx.x;
    long stride = (long)gridDim.x * blockDim.x;
    for (; i < n4; i += stride) {
        float4 v = reinterpret_cast<const float4*>(in)[i];
        uint32_t hx = f2h(v.x), hy = f2h(v.y), hz = f2h(v.z), hw = f2h(v.w);
        reinterpret_cast<uint2*>(h)[i] = make_uint2(hx | (hy << 16), hz | (hw << 16));
    }
}

// ---------------- router (with fused dispatch scan) ----------------
__global__ void __launch_bounds__(256) router_kernel(
    const float* __restrict__ x, const int* __restrict__ mask,
    const float* __restrict__ noise, const float* __restrict__ Wr, int N, int D)
{
    int warp = threadIdx.x >> 5, lane = threadIdx.x & 31;
    int t = blockIdx.x * 8 + warp;
    __shared__ float s_log[8][16];
    __shared__ float s_p[16]; __shared__ int s_f[16];
    __shared__ float s_z; __shared__ int s_n;
    if (threadIdx.x < 16) { s_p[threadIdx.x] = 0.f; s_f[threadIdx.x] = 0; }
    if (threadIdx.x == 0) { s_z = 0.f; s_n = 0; }
    __syncthreads();
    if (t < N) {
        float acc[16];
#pragma unroll
        for (int e = 0; e < 16; ++e) acc[e] = 0.f;
        const float* xr = x + (size_t)t * D;
        for (int d = lane; d < D; d += 32) {
            float xv = xr[d];
            const float* w = Wr + (size_t)d * 16;
#pragma unroll
            for (int e = 0; e < 16; ++e) acc[e] = fmaf(xv, w[e], acc[e]);
        }
#pragma unroll
        for (int e = 0; e < 16; ++e) {
            float v = acc[e];
#pragma unroll
            for (int o = 16; o; o >>= 1) v += __shfl_xor_sync(0xFFFFFFFFu, v, o);
            if (lane == 0) s_log[warp][e] = v;
        }
        __syncwarp();
        int e = lane & 15;
        float lc = s_log[warp][e];
        int mk = mask[t] ? 1 : 0;
        float nz = noise[(size_t)t * 16 + e];
        float mult = mk ? (1.0f + (nz * 2.0f - 1.0f) * 0.1f) : 1.0f;
        float ln = lc * mult;
        float mx = ln;
#pragma unroll
        for (int o = 8; o; o >>= 1) mx = fmaxf(mx, __shfl_xor_sync(0xFFFFFFFFu, mx, o, 16));
        unsigned bal = __ballot_sync(0xFFFFFFFFu, ln == mx);
        int eid = __ffs(bal) - 1;
        float se = expf(ln - mx);
#pragma unroll
        for (int o = 8; o; o >>= 1) se += __shfl_xor_sync(0xFFFFFFFFu, se, o, 16);
        float lse = mx + logf(se);
        float gate = expf(mx - lse);
        float mxc = lc;
#pragma unroll
        for (int o = 8; o; o >>= 1) mxc = fmaxf(mxc, __shfl_xor_sync(0xFFFFFFFFu, mxc, o, 16));
        unsigned balc = __ballot_sync(0xFFFFFFFFu, lc == mxc);
        int eidc = __ffs(balc) - 1;
        float sec = expf(lc - mxc);
#pragma unroll
        for (int o = 8; o; o >>= 1) sec += __shfl_xor_sync(0xFFFFFFFFu, sec, o, 16);
        float lsec = mxc + logf(sec);
        float pce = expf(lc - lsec);
        if (lane < 16 && mk) {
            atomicAdd(&s_p[e], pce);
            if (e == eidc) atomicAdd(&s_f[e], 1);
        }
        if (lane == 0) {
            g_gate[t] = gate;
            if (mk) {
                atomicAdd(&s_z, lsec * lsec); atomicAdd(&s_n, 1);
                int i = atomicAdd(&g_cnt[eid], 1);
                g_lst_tok[eid * NTOK + i] = t;
                g_lst_gate[eid * NTOK + i] = gate;
            }
        }
    }
    __syncthreads();
    if (threadIdx.x < 16) {
        g_pp[blockIdx.x * 16 + threadIdx.x] = s_p[threadIdx.x];
        g_pf[blockIdx.x * 16 + threadIdx.x] = s_f[threadIdx.x];
    }
    if (threadIdx.x == 0) { g_pz[blockIdx.x] = s_z; g_pn[blockIdx.x] = s_n; }
}

__global__ void loss_reduce_kernel(float* __restrict__ out, int nb, long outsz) {
    __shared__ float sp[16], sf[16], szn[2];
    int tid = threadIdx.x;
    if (tid < 16) {
        float s = 0.f; int c = 0;
        for (int b = 0; b < nb; ++b) { s += g_pp[b * 16 + tid]; c += g_pf[b * 16 + tid]; }
        sp[tid] = s; sf[tid] = (float)c;
    }
    if (tid == 16) { float s = 0.f; for (int b = 0; b < nb; ++b) s += g_pz[b]; szn[0] = s; }
    if (tid == 17) { int c = 0; for (int b = 0; b < nb; ++b) c += g_pn[b]; szn[1] = (float)c; }
    __syncthreads();
    if (tid == 0) {
        float n = szn[1], lb = 0.f;
        for (int e = 0; e < 16; ++e) lb += (sp[e] / n) * (sf[e] / n);
        out[outsz - 2] = lb * 16.0f;
        out[outsz - 1] = szn[0] / n;
    }
}

// ---------------- per-expert slot assignment ----------------
// Fast path (cnt <= cap): no token is dropped, so ANY slot<->token bijection
// yields identical y — use arrival order. Fallback: exact lexsort rank.
__global__ void __launch_bounds__(256) rank_kernel(int cap)
{
    extern __shared__ char dsm[];
    float* sg = (float*)dsm;
    int*   st = (int*)(dsm + (size_t)NTOK * 4);
    int e = blockIdx.x, tid = threadIdx.x;
    int cnt = g_cnt[e];

    if (cnt <= cap) {
        for (int i = tid; i < cnt; i += 256) {
            g_tok4slot[e * cap + i] = g_lst_tok[e * NTOK + i];
            g_slotgate[e * cap + i] = g_lst_gate[e * NTOK + i];
        }
        for (int i = cnt + tid; i < cap; i += 256) {
            g_tok4slot[e * cap + i] = -1;
            g_slotgate[e * cap + i] = 0.f;
        }
        return;
    }

    for (int i = tid; i < cap; i += 256) {
        g_tok4slot[e * cap + i] = -1;
        g_slotgate[e * cap + i] = 0.f;
    }
    for (int i = tid; i < cnt; i += 256) {
        st[i] = g_lst_tok[e * NTOK + i];
        sg[i] = g_lst_gate[e * NTOK + i];
    }
    __syncthreads();
    for (int i = tid; i < cnt; i += 256) {
        int ti = st[i]; float gi = sg[i];
        int r = 0;
        for (int j = 0; j < cnt; ++j) {
            float gj = sg[j]; int tj = st[j];
            r += (gj > gi) || (gj == gi && tj < ti);
        }
        if (r < cap) {
            g_tok4slot[e * cap + r] = ti;
            g_slotgate[e * cap + r] = gi;
        }
    }
}

// ---------------- fp16 tensor-core GEMM, BK=64, fp32 B converted in-kernel ----
// CTA tile 128m x 128n, 8 warps (4m x 2n), warp tile 32x64.
// A: packed fp16 (g_xh / g_hh), double-buffered cp.async.
// B: fp32 weights cp.async'd into a SINGLE staging buffer, converted to a
//    double-buffered swizzled fp16 tile right after arrival (thread-own data).
// MODE 0: h = relu(gather(x) @ W1[e]), KSPLIT=1, store epilogue.
// MODE 1: y += (h @ W2[e]) * gate over KSPLIT=4 segments, atomicAdd epilogue.
#define APITCH 144
#define ABUF(s)  ((s) * 18432)
#define BCVT(s)  (36864 + (s) * 16384)
#define BSTG     69632
#define GSMEM    102400

template<int MODE, int KSPLIT>
__global__ void __launch_bounds__(256, 2) gemm_kernel(
    const float* __restrict__ W, float* __restrict__ y, int cap)
{
    const int KTOT = (MODE == 0) ? 1024 : 4096;
    const int KSEG = KTOT / KSPLIT;
    const int NT   = (MODE == 0) ? 32 : 8;
    const int Nn   = (MODE == 0) ? 4096 : 1024;
    const int NCH  = KSEG / 64;

    int b = blockIdx.x;
    const int m  = b % 5; b /= 5;
    const int n  = b % NT; b /= NT;
    const int kq = b % KSPLIT;
    const int e  = b / KSPLIT;
    const int m0 = m * 128, n0 = n * 128;

    if (m0 >= g_cnt[e]) return;   // empty m-tile: outputs all discarded

    extern __shared__ char smem[];
    const uint32_t sb = smem_u32(smem);
    __shared__ int s_arow[128];

    const int tid = threadIdx.x, wid = tid >> 5, lane = tid & 31;
    const int wm = wid & 3, wn = wid >> 2;

    if (tid < 128) {
        if (MODE == 0) {
            int tok = g_tok4slot[e * cap + m0 + tid];
            s_arow[tid] = (tok >= 0) ? tok : 0;
        } else {
            s_arow[tid] = e * CAPS + m0 + tid;
        }
    }
    __syncthreads();

    const ushort_t* AH = ((MODE == 0) ? g_xh : g_hh) + (size_t)kq * KSEG;
    const float* BW = W + (size_t)e * KTOT * Nn + (size_t)kq * KSEG * Nn;

    // A cp.async coordinates: 4 slots (128 rows x 8 chunks of 16B)
    const ushort_t* aP[4];
    uint32_t aOff[4];
#pragma unroll
    for (int i = 0; i < 4; ++i) {
        int ia = tid + i * 256;
        int ar = ia >> 3, ac = ia & 7;
        aP[i] = AH + (size_t)s_arow[ar] * KTOT + ac * 8;
        aOff[i] = ar * APITCH + ac * 16;
    }
    // B fp32 staging: thread owns row br = tid>>2, quarter q4 = tid&3 (32 floats)
    const int br = tid >> 2, q4 = tid & 3;
    const float* bsrc = BW + (size_t)br * Nn + n0 + q4 * 32;
    const uint32_t bstg = sb + BSTG + br * 512 + q4 * 128;

    float acc[2][8][4];
#pragma unroll
    for (int i = 0; i < 2; ++i)
#pragma unroll
        for (int j = 0; j < 8; ++j)
#pragma unroll
            for (int q = 0; q < 4; ++q) acc[i][j][q] = 0.f;

    auto issue = [&](int kt, int buf) {
        const long ka = (long)kt * 64;
#pragma unroll
        for (int i = 0; i < 4; ++i) cpa16(sb + ABUF(buf) + aOff[i], aP[i] + ka);
        const float* bs = bsrc + (size_t)kt * 64 * Nn;
#pragma unroll
        for (int q = 0; q < 8; ++q) cpa16(bstg + q * 16, bs + q * 4);
        cp_commit();
    };

    issue(0, 0);

    const uint32_t a_row = (lane & 15), a_kq = (lane >> 4);
    const uint32_t b_kr = (lane & 7) + (lane >> 4) * 8;
    const uint32_t b_nc = wn * 8 + ((lane >> 3) & 1);

    for (int kt = 0; kt < NCH; ++kt) {
        const int buf = kt & 1;
        cp_wait0();
        __syncthreads();   // staged data visible; all warps done with compute(kt-1)

        // convert own staged fp32 (32 floats) -> swizzled fp16 tile
        {
            const char* src = smem + BSTG + br * 512 + q4 * 128;
            char* dst = smem + BCVT(buf);
#pragma unroll
            for (int j = 0; j < 4; ++j) {
                float4 v0 = *(const float4*)(src + j * 32);
                float4 v1 = *(const float4*)(src + j * 32 + 16);
                uint4 hv;
                hv.x = f2h(v0.x) | (f2h(v0.y) << 16);
                hv.y = f2h(v0.z) | (f2h(v0.w) << 16);
                hv.z = f2h(v1.x) | (f2h(v1.y) << 16);
                hv.w = f2h(v1.z) | (f2h(v1.w) << 16);
                uint32_t bc = q4 * 4 + j;
                *(uint4*)(dst + br * 256 + ((bc ^ (br & 7)) << 4)) = hv;
            }
        }
        __syncthreads();   // fp16 tile visible; staging consumed -> free for kt+1
        if (kt + 1 < NCH) issue(kt + 1, buf ^ 1);

        const uint32_t aB = sb + ABUF(buf);
        const uint32_t bB = sb + BCVT(buf);

#pragma unroll
        for (int ks = 0; ks < 4; ++ks) {
            uint32_t fA[2][4];
#pragma unroll
            for (int tm = 0; tm < 2; ++tm) {
                uint32_t ao = (wm * 32 + tm * 16 + a_row) * APITCH + (ks * 16 + a_kq * 8) * 2;
                ldsm4(fA[tm], aB + ao);
            }
            const uint32_t kr = ks * 16 + b_kr;
            const uint32_t krl = kr & 7;
#pragma unroll
            for (int nb = 0; nb < 4; ++nb) {
                uint32_t nc = b_nc + nb * 2;
                uint32_t bo = kr * 256 + ((nc ^ krl) << 4);
                uint32_t fB[4];
                ldsm4t(fB, bB + bo);
#pragma unroll
                for (int tm = 0; tm < 2; ++tm) {
                    mmaf16(acc[tm][nb * 2 + 0], fA[tm], fB[0], fB[2]);
                    mmaf16(acc[tm][nb * 2 + 1], fA[tm], fB[1], fB[3]);
                }
            }
        }
    }

    // ---- epilogue ----
    const int gid = lane >> 2, tig = lane & 3;
#pragma unroll
    for (int tm = 0; tm < 2; ++tm) {
        const int r0 = m0 + wm * 32 + tm * 16 + gid;
#pragma unroll
        for (int j = 0; j < 8; ++j) {
            const int col = n0 + wn * 64 + j * 8 + tig * 2;
            if (MODE == 0) {
#pragma unroll
                for (int hh = 0; hh < 2; ++hh) {
                    int row = r0 + hh * 8;
                    float v0 = fmaxf(acc[tm][j][hh * 2 + 0], 0.f);
                    float v1 = fmaxf(acc[tm][j][hh * 2 + 1], 0.f);
                    uint32_t h0 = f2h(v0), h1 = f2h(v1);
                    size_t idx = (size_t)(e * CAPS + row) * 4096 + col;
                    *(uint32_t*)(g_hh + idx) = h0 | (h1 << 16);
                }
            } else {
#pragma unroll
                for (int hh = 0; hh < 2; ++hh) {
                    int row = r0 + hh * 8;
                    int slot = e * cap + row;
                    int tok = g_tok4slot[slot];
                    if (tok >= 0) {
                        float g = g_slotgate[slot];
                        float* dst = y + (size_t)tok * 1024 + col;
                        atomicAdd(dst + 0, acc[tm][j][hh * 2 + 0] * g);
                        atomicAdd(dst + 1, acc[tm][j][hh * 2 + 1] * g);
                    }
                }
            }
        }
    }
}

// ---------------- launch ----------------
extern "C" void kernel_launch(void* const* d_in, const int* in_sizes, int n_in,
                              void* d_out, int out_size)
{
    const float* x     = (const float*)d_in[0];
    const int*   mask  = (const int*)d_in[1];
    const float* noise = (const float*)d_in[2];
    const float* Wr    = (const float*)d_in[3];
    const float* W1    = (const float*)d_in[4];
    const float* W2    = (const float*)d_in[5];
    float*       out   = (float*)d_out;

    const int  N = in_sizes[1];                      // 8192
    const int  D = in_sizes[0] / N;                  // 1024
    const int  E = in_sizes[2] / N;                  // 16
    const int  H = (int)((long)in_sizes[4] / ((long)E * D)); // 4096
    const int  cap = (int)((long)N * 5 / (4 * E));   // 640
    const long ytot = (long)N * D;

    cudaFuncSetAttribute((const void*)gemm_kernel<0,1>, cudaFuncAttributeMaxDynamicSharedMemorySize, GSMEM);
    cudaFuncSetAttribute((const void*)gemm_kernel<1,4>, cudaFuncAttributeMaxDynamicSharedMemorySize, GSMEM);
    cudaFuncSetAttribute(rank_kernel, cudaFuncAttributeMaxDynamicSharedMemorySize, 65536);

    init_kernel<<<(unsigned)((ytot / 4 + 255) / 256), 256>>>(out, ytot);
    router_kernel<<<N / 8, 256>>>(x, mask, noise, Wr, N, D);
    loss_reduce_kernel<<<1, 32>>>(out, N / 8, (long)out_size);
    rank_kernel<<<E, 256, (size_t)N * 8>>>(cap);

    ushort_t* xh;
    cudaGetSymbolAddress((void**)&xh, g_xh);
    pack_kernel<<<2048, 256>>>(x, xh, (long)N * D / 4);

    gemm_kernel<0,1><<<E * (H / 128) * 5, 256, GSMEM>>>(W1, out, cap);
    gemm_kernel<1,4><<<E * (D / 128) * 5 * 4, 256, GSMEM>>>(W2, out, cap);
}

// round 15
// speedup vs baseline: 1.8699x; 1.8699x over previous
#include <cuda_runtime.h>
#include <cuda_fp16.h>
#include <cstdint>
#include <cstddef>

typedef unsigned short ushort_t;

#define NTOK 8192
#define EEXP 16
#define CAPS 640
#define RBLKS (NTOK/8)

// ---------------- static device scratch ----------------
__device__ ushort_t g_xh[(size_t)NTOK * 1024];
__device__ ushort_t g_w1h[(size_t)EEXP * 1024 * 4096];
__device__ ushort_t g_w2h[(size_t)EEXP * 4096 * 1024];
__device__ ushort_t g_hh[(size_t)EEXP * CAPS * 4096];
__device__ float g_gate[NTOK];
__device__ int   g_cnt[EEXP];
__device__ int   g_lst_tok[EEXP * NTOK];
__device__ float g_lst_gate[EEXP * NTOK];
__device__ int   g_tok4slot[EEXP * CAPS];
__device__ float g_slotgate[EEXP * CAPS];
__device__ float g_pp[RBLKS * 16];
__device__ int   g_pf[RBLKS * 16];
__device__ float g_pz[RBLKS];
__device__ int   g_pn[RBLKS];

// ---------------- helpers ----------------
__device__ __forceinline__ uint32_t f2h(float f) {
    return (uint32_t)__half_as_ushort(__float2half_rn(f));
}
__device__ __forceinline__ uint32_t smem_u32(const void* p) {
    uint32_t a;
    asm("{ .reg .u64 t; cvta.to.shared.u64 t, %1; cvt.u32.u64 %0, t; }" : "=r"(a) : "l"(p));
    return a;
}
__device__ __forceinline__ void cpa16(uint32_t d, const void* s) {
    asm volatile("cp.async.cg.shared.global [%0], [%1], 16;" :: "r"(d), "l"(s));
}
__device__ __forceinline__ void cp_commit() { asm volatile("cp.async.commit_group;"); }
__device__ __forceinline__ void cp_wait0() { asm volatile("cp.async.wait_group 0;" ::: "memory"); }
__device__ __forceinline__ void cp_wait1() { asm volatile("cp.async.wait_group 1;" ::: "memory"); }
__device__ __forceinline__ void ldsm4(uint32_t* r, uint32_t a) {
    asm volatile("ldmatrix.sync.aligned.m8n8.x4.shared.b16 {%0,%1,%2,%3}, [%4];"
        : "=r"(r[0]), "=r"(r[1]), "=r"(r[2]), "=r"(r[3]) : "r"(a));
}
__device__ __forceinline__ void ldsm4t(uint32_t* r, uint32_t a) {
    asm volatile("ldmatrix.sync.aligned.m8n8.x4.trans.shared.b16 {%0,%1,%2,%3}, [%4];"
        : "=r"(r[0]), "=r"(r[1]), "=r"(r[2]), "=r"(r[3]) : "r"(a));
}
__device__ __forceinline__ void mmaf16(float* c, const uint32_t* a, uint32_t b0, uint32_t b1) {
    asm volatile("mma.sync.aligned.m16n8k16.row.col.f32.f16.f16.f32 "
        "{%0,%1,%2,%3}, {%4,%5,%6,%7}, {%8,%9}, {%0,%1,%2,%3};"
        : "+f"(c[0]), "+f"(c[1]), "+f"(c[2]), "+f"(c[3])
        : "r"(a[0]), "r"(a[1]), "r"(a[2]), "r"(a[3]), "r"(b0), "r"(b1));
}

// ---------------- init: zero y + expert counters ----------------
__global__ void init_kernel(float* __restrict__ out, long ytot) {
    if (blockIdx.x == 0 && threadIdx.x < EEXP) g_cnt[threadIdx.x] = 0;
    long i4 = (long)blockIdx.x * blockDim.x + threadIdx.x;
    long n4 = ytot >> 2;
    long stride = (long)gridDim.x * blockDim.x;
    float4 z = make_float4(0.f, 0.f, 0.f, 0.f);
    for (; i4 < n4; i4 += stride) reinterpret_cast<float4*>(out)[i4] = z;
}

// ---------------- fp16 pack ----------------
__global__ void pack_kernel(const float* __restrict__ in, ushort_t* __restrict__ h, long n4)
{
    long i = (long)blockIdx.x * blockDim.x + threadIdx.x;
    long stride = (long)gridDim.x * blockDim.x;
    for (; i < n4; i += stride) {
        float4 v = reinterpret_cast<const float4*>(in)[i];
        uint32_t hx = f2h(v.x), hy = f2h(v.y), hz = f2h(v.z), hw = f2h(v.w);
        reinterpret_cast<uint2*>(h)[i] = make_uint2(hx | (hy << 16), hz | (hw << 16));
    }
}

// ---------------- router (with fused dispatch scan) ----------------
__global__ void __launch_bounds__(256) router_kernel(
    const float* __restrict__ x, const int* __restrict__ mask,
    const float* __restrict__ noise, const float* __restrict__ Wr, int N, int D)
{
    int warp = threadIdx.x >> 5, lane = threadIdx.x & 31;
    int t = blockIdx.x * 8 + warp;
    __shared__ float s_log[8][16];
    __shared__ float s_p[16]; __shared__ int s_f[16];
    __shared__ float s_z; __shared__ int s_n;
    if (threadIdx.x < 16) { s_p[threadIdx.x] = 0.f; s_f[threadIdx.x] = 0; }
    if (threadIdx.x == 0) { s_z = 0.f; s_n = 0; }
    __syncthreads();
    if (t < N) {
        float acc[16];
#pragma unroll
        for (int e = 0; e < 16; ++e) acc[e] = 0.f;
        const float* xr = x + (size_t)t * D;
        for (int d = lane; d < D; d += 32) {
            float xv = xr[d];
            const float* w = Wr + (size_t)d * 16;
#pragma unroll
            for (int e = 0; e < 16; ++e) acc[e] = fmaf(xv, w[e], acc[e]);
        }
#pragma unroll
        for (int e = 0; e < 16; ++e) {
            float v = acc[e];
#pragma unroll
            for (int o = 16; o; o >>= 1) v += __shfl_xor_sync(0xFFFFFFFFu, v, o);
            if (lane == 0) s_log[warp][e] = v;
        }
        __syncwarp();
        int e = lane & 15;
        float lc = s_log[warp][e];
        int mk = mask[t] ? 1 : 0;
        float nz = noise[(size_t)t * 16 + e];
        float mult = mk ? (1.0f + (nz * 2.0f - 1.0f) * 0.1f) : 1.0f;
        float ln = lc * mult;
        float mx = ln;
#pragma unroll
        for (int o = 8; o; o >>= 1) mx = fmaxf(mx, __shfl_xor_sync(0xFFFFFFFFu, mx, o, 16));
        unsigned bal = __ballot_sync(0xFFFFFFFFu, ln == mx);
        int eid = __ffs(bal) - 1;
        float se = expf(ln - mx);
#pragma unroll
        for (int o = 8; o; o >>= 1) se += __shfl_xor_sync(0xFFFFFFFFu, se, o, 16);
        float lse = mx + logf(se);
        float gate = expf(mx - lse);
        float mxc = lc;
#pragma unroll
        for (int o = 8; o; o >>= 1) mxc = fmaxf(mxc, __shfl_xor_sync(0xFFFFFFFFu, mxc, o, 16));
        unsigned balc = __ballot_sync(0xFFFFFFFFu, lc == mxc);
        int eidc = __ffs(balc) - 1;
        float sec = expf(lc - mxc);
#pragma unroll
        for (int o = 8; o; o >>= 1) sec += __shfl_xor_sync(0xFFFFFFFFu, sec, o, 16);
        float lsec = mxc + logf(sec);
        float pce = expf(lc - lsec);
        if (lane < 16 && mk) {
            atomicAdd(&s_p[e], pce);
            if (e == eidc) atomicAdd(&s_f[e], 1);
        }
        if (lane == 0) {
            g_gate[t] = gate;
            if (mk) {
                atomicAdd(&s_z, lsec * lsec); atomicAdd(&s_n, 1);
                int i = atomicAdd(&g_cnt[eid], 1);
                g_lst_tok[eid * NTOK + i] = t;
                g_lst_gate[eid * NTOK + i] = gate;
            }
        }
    }
    __syncthreads();
    if (threadIdx.x < 16) {
        g_pp[blockIdx.x * 16 + threadIdx.x] = s_p[threadIdx.x];
        g_pf[blockIdx.x * 16 + threadIdx.x] = s_f[threadIdx.x];
    }
    if (threadIdx.x == 0) { g_pz[blockIdx.x] = s_z; g_pn[blockIdx.x] = s_n; }
}

__global__ void loss_reduce_kernel(float* __restrict__ out, int nb, long outsz) {
    __shared__ float sp[16], sf[16], szn[2];
    int tid = threadIdx.x;
    if (tid < 16) {
        float s = 0.f; int c = 0;
        for (int b = 0; b < nb; ++b) { s += g_pp[b * 16 + tid]; c += g_pf[b * 16 + tid]; }
        sp[tid] = s; sf[tid] = (float)c;
    }
    if (tid == 16) { float s = 0.f; for (int b = 0; b < nb; ++b) s += g_pz[b]; szn[0] = s; }
    if (tid == 17) { int c = 0; for (int b = 0; b < nb; ++b) c += g_pn[b]; szn[1] = (float)c; }
    __syncthreads();
    if (tid == 0) {
        float n = szn[1], lb = 0.f;
        for (int e = 0; e < 16; ++e) lb += (sp[e] / n) * (sf[e] / n);
        out[outsz - 2] = lb * 16.0f;
        out[outsz - 1] = szn[0] / n;
    }
}

// ---------------- per-expert slot assignment ----------------
// Fast path (cnt <= cap): no token dropped, any slot order gives identical y.
// Fallback: exact lexsort rank (only if cnt > cap).
__global__ void __launch_bounds__(256) rank_kernel(int cap)
{
    extern __shared__ char dsm[];
    float* sg = (float*)dsm;
    int*   st = (int*)(dsm + (size_t)NTOK * 4);
    int e = blockIdx.x, tid = threadIdx.x;
    int cnt = g_cnt[e];

    if (cnt <= cap) {
        for (int i = tid; i < cnt; i += 256) {
            g_tok4slot[e * cap + i] = g_lst_tok[e * NTOK + i];
            g_slotgate[e * cap + i] = g_lst_gate[e * NTOK + i];
        }
        for (int i = cnt + tid; i < cap; i += 256) {
            g_tok4slot[e * cap + i] = -1;
            g_slotgate[e * cap + i] = 0.f;
        }
        return;
    }

    for (int i = tid; i < cap; i += 256) {
        g_tok4slot[e * cap + i] = -1;
        g_slotgate[e * cap + i] = 0.f;
    }
    for (int i = tid; i < cnt; i += 256) {
        st[i] = g_lst_tok[e * NTOK + i];
        sg[i] = g_lst_gate[e * NTOK + i];
    }
    __syncthreads();
    for (int i = tid; i < cnt; i += 256) {
        int ti = st[i]; float gi = sg[i];
        int r = 0;
        for (int j = 0; j < cnt; ++j) {
            float gj = sg[j]; int tj = st[j];
            r += (gj > gi) || (gj == gi && tj < ti);
        }
        if (r < cap) {
            g_tok4slot[e * cap + r] = ti;
            g_slotgate[e * cap + r] = gi;
        }
    }
}

// ---------------- fp16 single-pass tensor-core GEMM, BK=64 (round-13 proven) ----
// CTA tile 128m x 128n, 8 warps (4m x 2n), warp tile 32x64.
// 2-stage cp.async pipeline, pre-packed fp16 A and B.
// Early-exit for m-tiles fully past g_cnt[e].
// MODE 0: h = relu(gather(x) @ W1[e]), KSPLIT=1, store epilogue.
// MODE 1: y += (h @ W2[e]) * gate over KSPLIT=4 segments, atomicAdd epilogue.
#define APITCH 144
#define STG (128 * APITCH + 64 * 256)   // 34816
#define ABUF(s) ((s) * STG)
#define BBUF(s) ((s) * STG + 128 * APITCH)
#define GSMEM (2 * STG)

template<int MODE, int KSPLIT>
__global__ void __launch_bounds__(256, 2) gemm_kernel(
    const float* __restrict__ xunused, float* __restrict__ y, int cap)
{
    const int KTOT = (MODE == 0) ? 1024 : 4096;
    const int KSEG = KTOT / KSPLIT;
    const int NT   = (MODE == 0) ? 32 : 8;
    const int Nn   = (MODE == 0) ? 4096 : 1024;
    const int NCH  = KSEG / 64;

    int b = blockIdx.x;
    const int m  = b % 5; b /= 5;
    const int n  = b % NT; b /= NT;
    const int kq = b % KSPLIT;
    const int e  = b / KSPLIT;
    const int m0 = m * 128, n0 = n * 128;

    if (m0 >= g_cnt[e]) return;   // empty m-tile: outputs all discarded

    extern __shared__ char smem[];
    const uint32_t sb = smem_u32(smem);
    __shared__ int s_arow[128];

    const int tid = threadIdx.x, wid = tid >> 5, lane = tid & 31;
    const int wm = wid & 3, wn = wid >> 2;

    if (tid < 128) {
        if (MODE == 0) {
            int tok = g_tok4slot[e * cap + m0 + tid];
            s_arow[tid] = (tok >= 0) ? tok : 0;
        } else {
            s_arow[tid] = e * CAPS + m0 + tid;
        }
    }
    __syncthreads();

    const ushort_t* AH = ((MODE == 0) ? g_xh : g_hh) + (size_t)kq * KSEG;
    const ushort_t* BH = ((MODE == 0) ? g_w1h : g_w2h)
                         + (size_t)e * KTOT * Nn + (size_t)kq * KSEG * Nn;

    // per-thread cp.async coordinates: 4 slots each for A and B
    const ushort_t* aP[4];
    const ushort_t* bP[4];
    uint32_t aOff[4], bOff[4];
#pragma unroll
    for (int i = 0; i < 4; ++i) {
        int ia = tid + i * 256;
        int ar = ia >> 3, ac = ia & 7;
        aP[i] = AH + (size_t)s_arow[ar] * KTOT + ac * 8;
        aOff[i] = ar * APITCH + ac * 16;
        int br = ia >> 4, bc = ia & 15;
        bP[i] = BH + (size_t)br * Nn + n0 + bc * 8;
        bOff[i] = br * 256 + ((bc ^ (br & 7)) << 4);
    }

    float acc[2][8][4];
#pragma unroll
    for (int i = 0; i < 2; ++i)
#pragma unroll
        for (int j = 0; j < 8; ++j)
#pragma unroll
            for (int q = 0; q < 4; ++q) acc[i][j][q] = 0.f;

    auto issue = [&](int kt, int buf) {
        const long ka = (long)kt * 64;
        const long kb = (long)kt * 64 * Nn;
#pragma unroll
        for (int i = 0; i < 4; ++i) cpa16(sb + ABUF(buf) + aOff[i], aP[i] + ka);
#pragma unroll
        for (int i = 0; i < 4; ++i) cpa16(sb + BBUF(buf) + bOff[i], bP[i] + kb);
        cp_commit();
    };

    issue(0, 0);

    const uint32_t a_row = (lane & 15), a_kq = (lane >> 4);
    const uint32_t b_kr = (lane & 7) + (lane >> 4) * 8;
    const uint32_t b_nc = wn * 8 + ((lane >> 3) & 1);

    for (int kt = 0; kt < NCH; ++kt) {
        const int buf = kt & 1;
        if (kt + 1 < NCH) { issue(kt + 1, buf ^ 1); cp_wait1(); }
        else cp_wait0();
        __syncthreads();

        const uint32_t aB = sb + ABUF(buf);
        const uint32_t bB = sb + BBUF(buf);

#pragma unroll
        for (int ks = 0; ks < 4; ++ks) {
            uint32_t fA[2][4];
#pragma unroll
            for (int tm = 0; tm < 2; ++tm) {
                uint32_t ao = (wm * 32 + tm * 16 + a_row) * APITCH + (ks * 16 + a_kq * 8) * 2;
                ldsm4(fA[tm], aB + ao);
            }
            const uint32_t kr = ks * 16 + b_kr;
            const uint32_t krl = kr & 7;
#pragma unroll
            for (int nb = 0; nb < 4; ++nb) {
                uint32_t nc = b_nc + nb * 2;
                uint32_t bo = kr * 256 + ((nc ^ krl) << 4);
                uint32_t fB[4];
                ldsm4t(fB, bB + bo);
#pragma unroll
                for (int tm = 0; tm < 2; ++tm) {
                    mmaf16(acc[tm][nb * 2 + 0], fA[tm], fB[0], fB[2]);
                    mmaf16(acc[tm][nb * 2 + 1], fA[tm], fB[1], fB[3]);
                }
            }
        }
        __syncthreads();
    }

    // ---- epilogue ----
    const int gid = lane >> 2, tig = lane & 3;
#pragma unroll
    for (int tm = 0; tm < 2; ++tm) {
        const int r0 = m0 + wm * 32 + tm * 16 + gid;
#pragma unroll
        for (int j = 0; j < 8; ++j) {
            const int col = n0 + wn * 64 + j * 8 + tig * 2;
            if (MODE == 0) {
#pragma unroll
                for (int hh = 0; hh < 2; ++hh) {
                    int row = r0 + hh * 8;
                    float v0 = fmaxf(acc[tm][j][hh * 2 + 0], 0.f);
                    float v1 = fmaxf(acc[tm][j][hh * 2 + 1], 0.f);
                    uint32_t h0 = f2h(v0), h1 = f2h(v1);
                    size_t idx = (size_t)(e * CAPS + row) * 4096 + col;
                    *(uint32_t*)(g_hh + idx) = h0 | (h1 << 16);
                }
            } else {
#pragma unroll
                for (int hh = 0; hh < 2; ++hh) {
                    int row = r0 + hh * 8;
                    int slot = e * cap + row;
                    int tok = g_tok4slot[slot];
                    if (tok >= 0) {
                        float g = g_slotgate[slot];
                        float* dst = y + (size_t)tok * 1024 + col;
                        atomicAdd(dst + 0, acc[tm][j][hh * 2 + 0] * g);
                        atomicAdd(dst + 1, acc[tm][j][hh * 2 + 1] * g);
                    }
                }
            }
        }
    }
}

// ---------------- launch ----------------
extern "C" void kernel_launch(void* const* d_in, const int* in_sizes, int n_in,
                              void* d_out, int out_size)
{
    const float* x     = (const float*)d_in[0];
    const int*   mask  = (const int*)d_in[1];
    const float* noise = (const float*)d_in[2];
    const float* Wr    = (const float*)d_in[3];
    const float* W1    = (const float*)d_in[4];
    const float* W2    = (const float*)d_in[5];
    float*       out   = (float*)d_out;

    const int  N = in_sizes[1];                      // 8192
    const int  D = in_sizes[0] / N;                  // 1024
    const int  E = in_sizes[2] / N;                  // 16
    const int  H = (int)((long)in_sizes[4] / ((long)E * D)); // 4096
    const int  cap = (int)((long)N * 5 / (4 * E));   // 640
    const long ytot = (long)N * D;

    cudaFuncSetAttribute((const void*)gemm_kernel<0,1>, cudaFuncAttributeMaxDynamicSharedMemorySize, GSMEM);
    cudaFuncSetAttribute((const void*)gemm_kernel<1,4>, cudaFuncAttributeMaxDynamicSharedMemorySize, GSMEM);
    cudaFuncSetAttribute(rank_kernel, cudaFuncAttributeMaxDynamicSharedMemorySize, 65536);

    init_kernel<<<(unsigned)((ytot / 4 + 255) / 256), 256>>>(out, ytot);
    router_kernel<<<N / 8, 256>>>(x, mask, noise, Wr, N, D);
    loss_reduce_kernel<<<1, 32>>>(out, N / 8, (long)out_size);
    rank_kernel<<<E, 256, (size_t)N * 8>>>(cap);

    ushort_t *xh, *w1h, *w2h;
    cudaGetSymbolAddress((void**)&xh, g_xh);
    cudaGetSymbolAddress((void**)&w1h, g_w1h);
    cudaGetSymbolAddress((void**)&w2h, g_w2h);

    pack_kernel<<<2048, 256>>>(x, xh, (long)N * D / 4);
    pack_kernel<<<4096, 256>>>(W1, w1h, (long)E * D * H / 4);
    pack_kernel<<<4096, 256>>>(W2, w2h, (long)E * D * H / 4);

    gemm_kernel<0,1><<<E * (H / 128) * 5, 256, GSMEM>>>(x, out, cap);
    gemm_kernel<1,4><<<E * (D / 128) * 5 * 4, 256, GSMEM>>>(x, out, cap);
}

// round 16
// speedup vs baseline: 1.9188x; 1.0262x over previous
#include <cuda_runtime.h>
#include <cuda_fp16.h>
#include <cstdint>
#include <cstddef>

typedef unsigned short ushort_t;

#define NTOK 8192
#define EEXP 16
#define CAPS 640
#define RBLKS (NTOK/8)

// ---------------- static device scratch ----------------
__device__ ushort_t g_xh[(size_t)NTOK * 1024];
__device__ ushort_t g_w1h[(size_t)EEXP * 1024 * 4096];
__device__ ushort_t g_w2h[(size_t)EEXP * 4096 * 1024];
__device__ ushort_t g_hh[(size_t)EEXP * CAPS * 4096];
__device__ float g_gate[NTOK];
__device__ int   g_cnt[EEXP];
__device__ int   g_lst_tok[EEXP * NTOK];
__device__ float g_lst_gate[EEXP * NTOK];
__device__ int   g_tok4slot[EEXP * CAPS];
__device__ float g_slotgate[EEXP * CAPS];
__device__ float g_pp[RBLKS * 16];
__device__ int   g_pf[RBLKS * 16];
__device__ float g_pz[RBLKS];
__device__ int   g_pn[RBLKS];

// ---------------- helpers ----------------
__device__ __forceinline__ uint32_t f2h(float f) {
    return (uint32_t)__half_as_ushort(__float2half_rn(f));
}
__device__ __forceinline__ uint32_t smem_u32(const void* p) {
    uint32_t a;
    asm("{ .reg .u64 t; cvta.to.shared.u64 t, %1; cvt.u32.u64 %0, t; }" : "=r"(a) : "l"(p));
    return a;
}
__device__ __forceinline__ void cpa16(uint32_t d, const void* s) {
    asm volatile("cp.async.cg.shared.global [%0], [%1], 16;" :: "r"(d), "l"(s));
}
__device__ __forceinline__ void cp_commit() { asm volatile("cp.async.commit_group;"); }
__device__ __forceinline__ void cp_wait0() { asm volatile("cp.async.wait_group 0;" ::: "memory"); }
__device__ __forceinline__ void cp_wait1() { asm volatile("cp.async.wait_group 1;" ::: "memory"); }
__device__ __forceinline__ void ldsm4(uint32_t* r, uint32_t a) {
    asm volatile("ldmatrix.sync.aligned.m8n8.x4.shared.b16 {%0,%1,%2,%3}, [%4];"
        : "=r"(r[0]), "=r"(r[1]), "=r"(r[2]), "=r"(r[3]) : "r"(a));
}
__device__ __forceinline__ void ldsm4t(uint32_t* r, uint32_t a) {
    asm volatile("ldmatrix.sync.aligned.m8n8.x4.trans.shared.b16 {%0,%1,%2,%3}, [%4];"
        : "=r"(r[0]), "=r"(r[1]), "=r"(r[2]), "=r"(r[3]) : "r"(a));
}
__device__ __forceinline__ void mmaf16(float* c, const uint32_t* a, uint32_t b0, uint32_t b1) {
    asm volatile("mma.sync.aligned.m16n8k16.row.col.f32.f16.f16.f32 "
        "{%0,%1,%2,%3}, {%4,%5,%6,%7}, {%8,%9}, {%0,%1,%2,%3};"
        : "+f"(c[0]), "+f"(c[1]), "+f"(c[2]), "+f"(c[3])
        : "r"(a[0]), "r"(a[1]), "r"(a[2]), "r"(a[3]), "r"(b0), "r"(b1));
}
__device__ __forceinline__ void red_add_v2(float* dst, float a, float b) {
    asm volatile("red.global.add.v2.f32 [%0], {%1, %2};"
        :: "l"(dst), "f"(a), "f"(b) : "memory");
}

// ---------------- init: zero y + expert counters ----------------
__global__ void init_kernel(float* __restrict__ out, long ytot) {
    if (blockIdx.x == 0 && threadIdx.x < EEXP) g_cnt[threadIdx.x] = 0;
    long i4 = (long)blockIdx.x * blockDim.x + threadIdx.x;
    long n4 = ytot >> 2;
    long stride = (long)gridDim.x * blockDim.x;
    float4 z = make_float4(0.f, 0.f, 0.f, 0.f);
    for (; i4 < n4; i4 += stride) reinterpret_cast<float4*>(out)[i4] = z;
}

// ---------------- fp16 pack ----------------
__global__ void pack_kernel(const float* __restrict__ in, ushort_t* __restrict__ h, long n4)
{
    long i = (long)blockIdx.x * blockDim.x + threadIdx.x;
    long stride = (long)gridDim.x * blockDim.x;
    for (; i < n4; i += stride) {
        float4 v = reinterpret_cast<const float4*>(in)[i];
        uint32_t hx = f2h(v.x), hy = f2h(v.y), hz = f2h(v.z), hw = f2h(v.w);
        reinterpret_cast<uint2*>(h)[i] = make_uint2(hx | (hy << 16), hz | (hw << 16));
    }
}

// ---------------- router (with fused dispatch scan) ----------------
__global__ void __launch_bounds__(256) router_kernel(
    const float* __restrict__ x, const int* __restrict__ mask,
    const float* __restrict__ noise, const float* __restrict__ Wr, int N, int D)
{
    int warp = threadIdx.x >> 5, lane = threadIdx.x & 31;
    int t = blockIdx.x * 8 + warp;
    __shared__ float s_log[8][16];
    __shared__ float s_p[16]; __shared__ int s_f[16];
    __shared__ float s_z; __shared__ int s_n;
    if (threadIdx.x < 16) { s_p[threadIdx.x] = 0.f; s_f[threadIdx.x] = 0; }
    if (threadIdx.x == 0) { s_z = 0.f; s_n = 0; }
    __syncthreads();
    if (t < N) {
        float acc[16];
#pragma unroll
        for (int e = 0; e < 16; ++e) acc[e] = 0.f;
        const float* xr = x + (size_t)t * D;
        for (int d = lane; d < D; d += 32) {
            float xv = xr[d];
            const float* w = Wr + (size_t)d * 16;
#pragma unroll
            for (int e = 0; e < 16; ++e) acc[e] = fmaf(xv, w[e], acc[e]);
        }
#pragma unroll
        for (int e = 0; e < 16; ++e) {
            float v = acc[e];
#pragma unroll
            for (int o = 16; o; o >>= 1) v += __shfl_xor_sync(0xFFFFFFFFu, v, o);
            if (lane == 0) s_log[warp][e] = v;
        }
        __syncwarp();
        int e = lane & 15;
        float lc = s_log[warp][e];
        int mk = mask[t] ? 1 : 0;
        float nz = noise[(size_t)t * 16 + e];
        float mult = mk ? (1.0f + (nz * 2.0f - 1.0f) * 0.1f) : 1.0f;
        float ln = lc * mult;
        float mx = ln;
#pragma unroll
        for (int o = 8; o; o >>= 1) mx = fmaxf(mx, __shfl_xor_sync(0xFFFFFFFFu, mx, o, 16));
        unsigned bal = __ballot_sync(0xFFFFFFFFu, ln == mx);
        int eid = __ffs(bal) - 1;
        float se = expf(ln - mx);
#pragma unroll
        for (int o = 8; o; o >>= 1) se += __shfl_xor_sync(0xFFFFFFFFu, se, o, 16);
        float lse = mx + logf(se);
        float gate = expf(mx - lse);
        float mxc = lc;
#pragma unroll
        for (int o = 8; o; o >>= 1) mxc = fmaxf(mxc, __shfl_xor_sync(0xFFFFFFFFu, mxc, o, 16));
        unsigned balc = __ballot_sync(0xFFFFFFFFu, lc == mxc);
        int eidc = __ffs(balc) - 1;
        float sec = expf(lc - mxc);
#pragma unroll
        for (int o = 8; o; o >>= 1) sec += __shfl_xor_sync(0xFFFFFFFFu, sec, o, 16);
        float lsec = mxc + logf(sec);
        float pce = expf(lc - lsec);
        if (lane < 16 && mk) {
            atomicAdd(&s_p[e], pce);
            if (e == eidc) atomicAdd(&s_f[e], 1);
        }
        if (lane == 0) {
            g_gate[t] = gate;
            if (mk) {
                atomicAdd(&s_z, lsec * lsec); atomicAdd(&s_n, 1);
                int i = atomicAdd(&g_cnt[eid], 1);
                g_lst_tok[eid * NTOK + i] = t;
                g_lst_gate[eid * NTOK + i] = gate;
            }
        }
    }
    __syncthreads();
    if (threadIdx.x < 16) {
        g_pp[blockIdx.x * 16 + threadIdx.x] = s_p[threadIdx.x];
        g_pf[blockIdx.x * 16 + threadIdx.x] = s_f[threadIdx.x];
    }
    if (threadIdx.x == 0) { g_pz[blockIdx.x] = s_z; g_pn[blockIdx.x] = s_n; }
}

__global__ void loss_reduce_kernel(float* __restrict__ out, int nb, long outsz) {
    __shared__ float sp[16], sf[16], szn[2];
    int tid = threadIdx.x;
    if (tid < 16) {
        float s = 0.f; int c = 0;
        for (int b = 0; b < nb; ++b) { s += g_pp[b * 16 + tid]; c += g_pf[b * 16 + tid]; }
        sp[tid] = s; sf[tid] = (float)c;
    }
    if (tid == 16) { float s = 0.f; for (int b = 0; b < nb; ++b) s += g_pz[b]; szn[0] = s; }
    if (tid == 17) { int c = 0; for (int b = 0; b < nb; ++b) c += g_pn[b]; szn[1] = (float)c; }
    __syncthreads();
    if (tid == 0) {
        float n = szn[1], lb = 0.f;
        for (int e = 0; e < 16; ++e) lb += (sp[e] / n) * (sf[e] / n);
        out[outsz - 2] = lb * 16.0f;
        out[outsz - 1] = szn[0] / n;
    }
}

// ---------------- per-expert slot assignment ----------------
__global__ void __launch_bounds__(256) rank_kernel(int cap)
{
    extern __shared__ char dsm[];
    float* sg = (float*)dsm;
    int*   st = (int*)(dsm + (size_t)NTOK * 4);
    int e = blockIdx.x, tid = threadIdx.x;
    int cnt = g_cnt[e];

    if (cnt <= cap) {
        for (int i = tid; i < cnt; i += 256) {
            g_tok4slot[e * cap + i] = g_lst_tok[e * NTOK + i];
            g_slotgate[e * cap + i] = g_lst_gate[e * NTOK + i];
        }
        for (int i = cnt + tid; i < cap; i += 256) {
            g_tok4slot[e * cap + i] = -1;
            g_slotgate[e * cap + i] = 0.f;
        }
        return;
    }

    for (int i = tid; i < cap; i += 256) {
        g_tok4slot[e * cap + i] = -1;
        g_slotgate[e * cap + i] = 0.f;
    }
    for (int i = tid; i < cnt; i += 256) {
        st[i] = g_lst_tok[e * NTOK + i];
        sg[i] = g_lst_gate[e * NTOK + i];
    }
    __syncthreads();
    for (int i = tid; i < cnt; i += 256) {
        int ti = st[i]; float gi = sg[i];
        int r = 0;
        for (int j = 0; j < cnt; ++j) {
            float gj = sg[j]; int tj = st[j];
            r += (gj > gi) || (gj == gi && tj < ti);
        }
        if (r < cap) {
            g_tok4slot[e * cap + r] = ti;
            g_slotgate[e * cap + r] = gi;
        }
    }
}

// ---------------- fp16 single-pass tensor-core GEMM, BK=64 ----------------
// CTA tile 128m x 128n, 8 warps (4m x 2n), warp tile 32x64.
// 2-stage cp.async pipeline, pre-packed fp16 A and B.
// Early-exit for m-tiles fully past g_cnt[e]; epilogue row skip past cnt.
// MODE 0: h = relu(gather(x) @ W1[e]), KSPLIT=1, store epilogue.
// MODE 1: y += (h @ W2[e]) * gate over KSPLIT=4 segments, red.v2 epilogue.
#define APITCH 144
#define STG (128 * APITCH + 64 * 256)   // 34816
#define ABUF(s) ((s) * STG)
#define BBUF(s) ((s) * STG + 128 * APITCH)
#define GSMEM (2 * STG)

template<int MODE, int KSPLIT>
__global__ void __launch_bounds__(256, 2) gemm_kernel(
    const float* __restrict__ xunused, float* __restrict__ y, int cap)
{
    const int KTOT = (MODE == 0) ? 1024 : 4096;
    const int KSEG = KTOT / KSPLIT;
    const int NT   = (MODE == 0) ? 32 : 8;
    const int Nn   = (MODE == 0) ? 4096 : 1024;
    const int NCH  = KSEG / 64;

    int b = blockIdx.x;
    const int m  = b % 5; b /= 5;
    const int n  = b % NT; b /= NT;
    const int kq = b % KSPLIT;
    const int e  = b / KSPLIT;
    const int m0 = m * 128, n0 = n * 128;

    const int cnt = g_cnt[e];
    if (m0 >= cnt) return;   // empty m-tile: outputs all discarded

    extern __shared__ char smem[];
    const uint32_t sb = smem_u32(smem);
    __shared__ int s_arow[128];

    const int tid = threadIdx.x, wid = tid >> 5, lane = tid & 31;
    const int wm = wid & 3, wn = wid >> 2;

    if (tid < 128) {
        if (MODE == 0) {
            int tok = g_tok4slot[e * cap + m0 + tid];
            s_arow[tid] = (tok >= 0) ? tok : 0;
        } else {
            s_arow[tid] = e * CAPS + m0 + tid;
        }
    }
    __syncthreads();

    const ushort_t* AH = ((MODE == 0) ? g_xh : g_hh) + (size_t)kq * KSEG;
    const ushort_t* BH = ((MODE == 0) ? g_w1h : g_w2h)
                         + (size_t)e * KTOT * Nn + (size_t)kq * KSEG * Nn;

    // per-thread cp.async coordinates: 4 slots each for A and B
    const ushort_t* aP[4];
    const ushort_t* bP[4];
    uint32_t aOff[4], bOff[4];
#pragma unroll
    for (int i = 0; i < 4; ++i) {
        int ia = tid + i * 256;
        int ar = ia >> 3, ac = ia & 7;
        aP[i] = AH + (size_t)s_arow[ar] * KTOT + ac * 8;
        aOff[i] = ar * APITCH + ac * 16;
        int br = ia >> 4, bc = ia & 15;
        bP[i] = BH + (size_t)br * Nn + n0 + bc * 8;
        bOff[i] = br * 256 + ((bc ^ (br & 7)) << 4);
    }

    float acc[2][8][4];
#pragma unroll
    for (int i = 0; i < 2; ++i)
#pragma unroll
        for (int j = 0; j < 8; ++j)
#pragma unroll
            for (int q = 0; q < 4; ++q) acc[i][j][q] = 0.f;

    auto issue = [&](int kt, int buf) {
        const long ka = (long)kt * 64;
        const long kb = (long)kt * 64 * Nn;
#pragma unroll
        for (int i = 0; i < 4; ++i) cpa16(sb + ABUF(buf) + aOff[i], aP[i] + ka);
#pragma unroll
        for (int i = 0; i < 4; ++i) cpa16(sb + BBUF(buf) + bOff[i], bP[i] + kb);
        cp_commit();
    };

    issue(0, 0);

    const uint32_t a_row = (lane & 15), a_kq = (lane >> 4);
    const uint32_t b_kr = (lane & 7) + (lane >> 4) * 8;
    const uint32_t b_nc = wn * 8 + ((lane >> 3) & 1);

    for (int kt = 0; kt < NCH; ++kt) {
        const int buf = kt & 1;
        if (kt + 1 < NCH) { issue(kt + 1, buf ^ 1); cp_wait1(); }
        else cp_wait0();
        __syncthreads();

        const uint32_t aB = sb + ABUF(buf);
        const uint32_t bB = sb + BBUF(buf);

#pragma unroll
        for (int ks = 0; ks < 4; ++ks) {
            uint32_t fA[2][4];
#pragma unroll
            for (int tm = 0; tm < 2; ++tm) {
                uint32_t ao = (wm * 32 + tm * 16 + a_row) * APITCH + (ks * 16 + a_kq * 8) * 2;
                ldsm4(fA[tm], aB + ao);
            }
            const uint32_t kr = ks * 16 + b_kr;
            const uint32_t krl = kr & 7;
#pragma unroll
            for (int nb = 0; nb < 4; ++nb) {
                uint32_t nc = b_nc + nb * 2;
                uint32_t bo = kr * 256 + ((nc ^ krl) << 4);
                uint32_t fB[4];
                ldsm4t(fB, bB + bo);
#pragma unroll
                for (int tm = 0; tm < 2; ++tm) {
                    mmaf16(acc[tm][nb * 2 + 0], fA[tm], fB[0], fB[2]);
                    mmaf16(acc[tm][nb * 2 + 1], fA[tm], fB[1], fB[3]);
                }
            }
        }
        __syncthreads();
    }

    // ---- epilogue ----
    const int gid = lane >> 2, tig = lane & 3;
#pragma unroll
    for (int tm = 0; tm < 2; ++tm) {
        const int r0 = m0 + wm * 32 + tm * 16 + gid;
#pragma unroll
        for (int j = 0; j < 8; ++j) {
            const int col = n0 + wn * 64 + j * 8 + tig * 2;
            if (MODE == 0) {
#pragma unroll
                for (int hh = 0; hh < 2; ++hh) {
                    int row = r0 + hh * 8;
                    if (row >= cnt) continue;   // h discarded downstream
                    float v0 = fmaxf(acc[tm][j][hh * 2 + 0], 0.f);
                    float v1 = fmaxf(acc[tm][j][hh * 2 + 1], 0.f);
                    uint32_t h0 = f2h(v0), h1 = f2h(v1);
                    size_t idx = (size_t)(e * CAPS + row) * 4096 + col;
                    *(uint32_t*)(g_hh + idx) = h0 | (h1 << 16);
                }
            } else {
#pragma unroll
                for (int hh = 0; hh < 2; ++hh) {
                    int row = r0 + hh * 8;
                    int slot = e * cap + row;
                    int tok = g_tok4slot[slot];
                    if (tok >= 0) {
                        float g = g_slotgate[slot];
                        red_add_v2(y + (size_t)tok * 1024 + col,
                                   acc[tm][j][hh * 2 + 0] * g,
                                   acc[tm][j][hh * 2 + 1] * g);
                    }
                }
            }
        }
    }
}

// ---------------- launch ----------------
extern "C" void kernel_launch(void* const* d_in, const int* in_sizes, int n_in,
                              void* d_out, int out_size)
{
    const float* x     = (const float*)d_in[0];
    const int*   mask  = (const int*)d_in[1];
    const float* noise = (const float*)d_in[2];
    const float* Wr    = (const float*)d_in[3];
    const float* W1    = (const float*)d_in[4];
    const float* W2    = (const float*)d_in[5];
    float*       out   = (float*)d_out;

    const int  N = in_sizes[1];                      // 8192
    const int  D = in_sizes[0] / N;                  // 1024
    const int  E = in_sizes[2] / N;                  // 16
    const int  H = (int)((long)in_sizes[4] / ((long)E * D)); // 4096
    const int  cap = (int)((long)N * 5 / (4 * E));   // 640
    const long ytot = (long)N * D;

    cudaFuncSetAttribute((const void*)gemm_kernel<0,1>, cudaFuncAttributeMaxDynamicSharedMemorySize, GSMEM);
    cudaFuncSetAttribute((const void*)gemm_kernel<1,4>, cudaFuncAttributeMaxDynamicSharedMemorySize, GSMEM);
    cudaFuncSetAttribute(rank_kernel, cudaFuncAttributeMaxDynamicSharedMemorySize, 65536);

    ushort_t *xh, *w1h, *w2h;
    cudaGetSymbolAddress((void**)&xh, g_xh);
    cudaGetSymbolAddress((void**)&w1h, g_w1h);
    cudaGetSymbolAddress((void**)&w2h, g_w2h);

    init_kernel<<<(unsigned)((ytot / 4 + 255) / 256), 256>>>(out, ytot);
    pack_kernel<<<2048, 256>>>(x, xh, (long)N * D / 4);
    router_kernel<<<N / 8, 256>>>(x, mask, noise, Wr, N, D);
    loss_reduce_kernel<<<1, 32>>>(out, N / 8, (long)out_size);
    rank_kernel<<<E, 256, (size_t)N * 8>>>(cap);
    pack_kernel<<<4096, 256>>>(W1, w1h, (long)E * D * H / 4);
    pack_kernel<<<4096, 256>>>(W2, w2h, (long)E * D * H / 4);

    gemm_kernel<0,1><<<E * (H / 128) * 5, 256, GSMEM>>>(x, out, cap);
    gemm_kernel<1,4><<<E * (D / 128) * 5 * 4, 256, GSMEM>>>(x, out, cap);
}

// round 17
// speedup vs baseline: 2.0654x; 1.0764x over previous
#include <cuda_runtime.h>
#include <cuda_fp16.h>
#include <cstdint>
#include <cstddef>

typedef unsigned short ushort_t;

#define NTOK 8192
#define EEXP 16
#define CAPS 640

// ---------------- static device scratch ----------------
__device__ ushort_t g_xh[(size_t)NTOK * 1024];
__device__ ushort_t g_w1h[(size_t)EEXP * 1024 * 4096];
__device__ ushort_t g_w2h[(size_t)EEXP * 4096 * 1024];
__device__ ushort_t g_hh[(size_t)EEXP * CAPS * 4096];
__device__ float g_gate[NTOK];
__device__ int   g_cnt[EEXP];
__device__ int   g_lst_tok[EEXP * NTOK];
__device__ float g_lst_gate[EEXP * NTOK];
__device__ int   g_tok4slot[EEXP * CAPS];
__device__ float g_slotgate[EEXP * CAPS];
__device__ float g_gp[EEXP];   // global sum of probs_clean per expert
__device__ int   g_gf[EEXP];   // global argmax-clean counts per expert
__device__ float g_gz;         // global sum of z^2
__device__ int   g_gn;         // global masked-token count

// ---------------- helpers ----------------
__device__ __forceinline__ uint32_t f2h(float f) {
    return (uint32_t)__half_as_ushort(__float2half_rn(f));
}
__device__ __forceinline__ uint32_t smem_u32(const void* p) {
    uint32_t a;
    asm("{ .reg .u64 t; cvta.to.shared.u64 t, %1; cvt.u32.u64 %0, t; }" : "=r"(a) : "l"(p));
    return a;
}
__device__ __forceinline__ void cpa16(uint32_t d, const void* s) {
    asm volatile("cp.async.cg.shared.global [%0], [%1], 16;" :: "r"(d), "l"(s));
}
__device__ __forceinline__ void cp_commit() { asm volatile("cp.async.commit_group;"); }
__device__ __forceinline__ void cp_wait0() { asm volatile("cp.async.wait_group 0;" ::: "memory"); }
__device__ __forceinline__ void cp_wait1() { asm volatile("cp.async.wait_group 1;" ::: "memory"); }
__device__ __forceinline__ void ldsm4(uint32_t* r, uint32_t a) {
    asm volatile("ldmatrix.sync.aligned.m8n8.x4.shared.b16 {%0,%1,%2,%3}, [%4];"
        : "=r"(r[0]), "=r"(r[1]), "=r"(r[2]), "=r"(r[3]) : "r"(a));
}
__device__ __forceinline__ void ldsm4t(uint32_t* r, uint32_t a) {
    asm volatile("ldmatrix.sync.aligned.m8n8.x4.trans.shared.b16 {%0,%1,%2,%3}, [%4];"
        : "=r"(r[0]), "=r"(r[1]), "=r"(r[2]), "=r"(r[3]) : "r"(a));
}
__device__ __forceinline__ void mmaf16(float* c, const uint32_t* a, uint32_t b0, uint32_t b1) {
    asm volatile("mma.sync.aligned.m16n8k16.row.col.f32.f16.f16.f32 "
        "{%0,%1,%2,%3}, {%4,%5,%6,%7}, {%8,%9}, {%0,%1,%2,%3};"
        : "+f"(c[0]), "+f"(c[1]), "+f"(c[2]), "+f"(c[3])
        : "r"(a[0]), "r"(a[1]), "r"(a[2]), "r"(a[3]), "r"(b0), "r"(b1));
}
__device__ __forceinline__ void red_add_v2(float* dst, float a, float b) {
    asm volatile("red.global.add.v2.f32 [%0], {%1, %2};"
        :: "l"(dst), "f"(a), "f"(b) : "memory");
}

// ---------------- init: zero y + counters + loss accumulators ----------------
__global__ void init_kernel(float* __restrict__ out, long ytot) {
    if (blockIdx.x == 0) {
        if (threadIdx.x < EEXP) {
            g_cnt[threadIdx.x] = 0;
            g_gp[threadIdx.x] = 0.f;
            g_gf[threadIdx.x] = 0;
        }
        if (threadIdx.x == 16) g_gz = 0.f;
        if (threadIdx.x == 17) g_gn = 0;
    }
    long i4 = (long)blockIdx.x * blockDim.x + threadIdx.x;
    long n4 = ytot >> 2;
    long stride = (long)gridDim.x * blockDim.x;
    float4 z = make_float4(0.f, 0.f, 0.f, 0.f);
    for (; i4 < n4; i4 += stride) reinterpret_cast<float4*>(out)[i4] = z;
}

// ---------------- fp16 pack ----------------
__global__ void pack_kernel(const float* __restrict__ in, ushort_t* __restrict__ h, long n4)
{
    long i = (long)blockIdx.x * blockDim.x + threadIdx.x;
    long stride = (long)gridDim.x * blockDim.x;
    for (; i < n4; i += stride) {
        float4 v = reinterpret_cast<const float4*>(in)[i];
        uint32_t hx = f2h(v.x), hy = f2h(v.y), hz = f2h(v.z), hw = f2h(v.w);
        reinterpret_cast<uint2*>(h)[i] = make_uint2(hx | (hy << 16), hz | (hw << 16));
    }
}

// ---------------- router (fused dispatch scan + global loss atomics) ----------
__global__ void __launch_bounds__(256) router_kernel(
    const float* __restrict__ x, const int* __restrict__ mask,
    const float* __restrict__ noise, const float* __restrict__ Wr, int N, int D)
{
    int warp = threadIdx.x >> 5, lane = threadIdx.x & 31;
    int t = blockIdx.x * 8 + warp;
    __shared__ float s_log[8][16];
    __shared__ float s_p[16]; __shared__ int s_f[16];
    __shared__ float s_z; __shared__ int s_n;
    if (threadIdx.x < 16) { s_p[threadIdx.x] = 0.f; s_f[threadIdx.x] = 0; }
    if (threadIdx.x == 0) { s_z = 0.f; s_n = 0; }
    __syncthreads();
    if (t < N) {
        float acc[16];
#pragma unroll
        for (int e = 0; e < 16; ++e) acc[e] = 0.f;
        const float* xr = x + (size_t)t * D;
        for (int d = lane; d < D; d += 32) {
            float xv = xr[d];
            const float* w = Wr + (size_t)d * 16;
#pragma unroll
            for (int e = 0; e < 16; ++e) acc[e] = fmaf(xv, w[e], acc[e]);
        }
#pragma unroll
        for (int e = 0; e < 16; ++e) {
            float v = acc[e];
#pragma unroll
            for (int o = 16; o; o >>= 1) v += __shfl_xor_sync(0xFFFFFFFFu, v, o);
            if (lane == 0) s_log[warp][e] = v;
        }
        __syncwarp();
        int e = lane & 15;
        float lc = s_log[warp][e];
        int mk = mask[t] ? 1 : 0;
        float nz = noise[(size_t)t * 16 + e];
        float mult = mk ? (1.0f + (nz * 2.0f - 1.0f) * 0.1f) : 1.0f;
        float ln = lc * mult;
        float mx = ln;
#pragma unroll
        for (int o = 8; o; o >>= 1) mx = fmaxf(mx, __shfl_xor_sync(0xFFFFFFFFu, mx, o, 16));
        unsigned bal = __ballot_sync(0xFFFFFFFFu, ln == mx);
        int eid = __ffs(bal) - 1;
        float se = expf(ln - mx);
#pragma unroll
        for (int o = 8; o; o >>= 1) se += __shfl_xor_sync(0xFFFFFFFFu, se, o, 16);
        float lse = mx + logf(se);
        float gate = expf(mx - lse);
        float mxc = lc;
#pragma unroll
        for (int o = 8; o; o >>= 1) mxc = fmaxf(mxc, __shfl_xor_sync(0xFFFFFFFFu, mxc, o, 16));
        unsigned balc = __ballot_sync(0xFFFFFFFFu, lc == mxc);
        int eidc = __ffs(balc) - 1;
        float sec = expf(lc - mxc);
#pragma unroll
        for (int o = 8; o; o >>= 1) sec += __shfl_xor_sync(0xFFFFFFFFu, sec, o, 16);
        float lsec = mxc + logf(sec);
        float pce = expf(lc - lsec);
        if (lane < 16 && mk) {
            atomicAdd(&s_p[e], pce);
            if (e == eidc) atomicAdd(&s_f[e], 1);
        }
        if (lane == 0) {
            g_gate[t] = gate;
            if (mk) {
                atomicAdd(&s_z, lsec * lsec); atomicAdd(&s_n, 1);
                int i = atomicAdd(&g_cnt[eid], 1);
                g_lst_tok[eid * NTOK + i] = t;
                g_lst_gate[eid * NTOK + i] = gate;
            }
        }
    }
    __syncthreads();
    // per-block partials -> global accumulators (one atomic each)
    if (threadIdx.x < 16) {
        atomicAdd(&g_gp[threadIdx.x], s_p[threadIdx.x]);
        atomicAdd(&g_gf[threadIdx.x], s_f[threadIdx.x]);
    }
    if (threadIdx.x == 16) atomicAdd(&g_gz, s_z);
    if (threadIdx.x == 17) atomicAdd(&g_gn, s_n);
}

// ---------------- loss finalize (trivial) ----------------
__global__ void loss_reduce_kernel(float* __restrict__ out, long outsz) {
    if (threadIdx.x == 0) {
        float n = (float)g_gn, lb = 0.f;
        for (int e = 0; e < 16; ++e) lb += (g_gp[e] / n) * ((float)g_gf[e] / n);
        out[outsz - 2] = lb * 16.0f;
        out[outsz - 1] = g_gz / n;
    }
}

// ---------------- per-expert slot assignment ----------------
__global__ void __launch_bounds__(256) rank_kernel(int cap)
{
    extern __shared__ char dsm[];
    float* sg = (float*)dsm;
    int*   st = (int*)(dsm + (size_t)NTOK * 4);
    int e = blockIdx.x, tid = threadIdx.x;
    int cnt = g_cnt[e];

    if (cnt <= cap) {
        for (int i = tid; i < cnt; i += 256) {
            g_tok4slot[e * cap + i] = g_lst_tok[e * NTOK + i];
            g_slotgate[e * cap + i] = g_lst_gate[e * NTOK + i];
        }
        for (int i = cnt + tid; i < cap; i += 256) {
            g_tok4slot[e * cap + i] = -1;
            g_slotgate[e * cap + i] = 0.f;
        }
        return;
    }

    for (int i = tid; i < cap; i += 256) {
        g_tok4slot[e * cap + i] = -1;
        g_slotgate[e * cap + i] = 0.f;
    }
    for (int i = tid; i < cnt; i += 256) {
        st[i] = g_lst_tok[e * NTOK + i];
        sg[i] = g_lst_gate[e * NTOK + i];
    }
    __syncthreads();
    for (int i = tid; i < cnt; i += 256) {
        int ti = st[i]; float gi = sg[i];
        int r = 0;
        for (int j = 0; j < cnt; ++j) {
            float gj = sg[j]; int tj = st[j];
            r += (gj > gi) || (gj == gi && tj < ti);
        }
        if (r < cap) {
            g_tok4slot[e * cap + r] = ti;
            g_slotgate[e * cap + r] = gi;
        }
    }
}

// ---------------- fp16 single-pass tensor-core GEMM, BK=64 ----------------
// CTA tile 128m x 128n, 8 warps (4m x 2n), warp tile 32x64.
// 2-stage cp.async pipeline, pre-packed fp16 A and B.
// Early-exit for m-tiles fully past g_cnt[e]; epilogue row skip past cnt.
// MODE 0: h = relu(gather(x) @ W1[e]), KSPLIT=1, store epilogue.
// MODE 1: y += (h @ W2[e]) * gate over KSPLIT=4 segments, red.v2 epilogue.
#define APITCH 144
#define STG (128 * APITCH + 64 * 256)   // 34816
#define ABUF(s) ((s) * STG)
#define BBUF(s) ((s) * STG + 128 * APITCH)
#define GSMEM (2 * STG)

template<int MODE, int KSPLIT>
__global__ void __launch_bounds__(256, 2) gemm_kernel(
    const float* __restrict__ xunused, float* __restrict__ y, int cap)
{
    const int KTOT = (MODE == 0) ? 1024 : 4096;
    const int KSEG = KTOT / KSPLIT;
    const int NT   = (MODE == 0) ? 32 : 8;
    const int Nn   = (MODE == 0) ? 4096 : 1024;
    const int NCH  = KSEG / 64;

    int b = blockIdx.x;
    const int m  = b % 5; b /= 5;
    const int n  = b % NT; b /= NT;
    const int kq = b % KSPLIT;
    const int e  = b / KSPLIT;
    const int m0 = m * 128, n0 = n * 128;

    const int cnt = g_cnt[e];
    if (m0 >= cnt) return;   // empty m-tile: outputs all discarded

    extern __shared__ char smem[];
    const uint32_t sb = smem_u32(smem);
    __shared__ int s_arow[128];

    const int tid = threadIdx.x, wid = tid >> 5, lane = tid & 31;
    const int wm = wid & 3, wn = wid >> 2;

    if (tid < 128) {
        if (MODE == 0) {
            int tok = g_tok4slot[e * cap + m0 + tid];
            s_arow[tid] = (tok >= 0) ? tok : 0;
        } else {
            s_arow[tid] = e * CAPS + m0 + tid;
        }
    }
    __syncthreads();

    const ushort_t* AH = ((MODE == 0) ? g_xh : g_hh) + (size_t)kq * KSEG;
    const ushort_t* BH = ((MODE == 0) ? g_w1h : g_w2h)
                         + (size_t)e * KTOT * Nn + (size_t)kq * KSEG * Nn;

    const ushort_t* aP[4];
    const ushort_t* bP[4];
    uint32_t aOff[4], bOff[4];
#pragma unroll
    for (int i = 0; i < 4; ++i) {
        int ia = tid + i * 256;
        int ar = ia >> 3, ac = ia & 7;
        aP[i] = AH + (size_t)s_arow[ar] * KTOT + ac * 8;
        aOff[i] = ar * APITCH + ac * 16;
        int br = ia >> 4, bc = ia & 15;
        bP[i] = BH + (size_t)br * Nn + n0 + bc * 8;
        bOff[i] = br * 256 + ((bc ^ (br & 7)) << 4);
    }

    float acc[2][8][4];
#pragma unroll
    for (int i = 0; i < 2; ++i)
#pragma unroll
        for (int j = 0; j < 8; ++j)
#pragma unroll
            for (int q = 0; q < 4; ++q) acc[i][j][q] = 0.f;

    auto issue = [&](int kt, int buf) {
        const long ka = (long)kt * 64;
        const long kb = (long)kt * 64 * Nn;
#pragma unroll
        for (int i = 0; i < 4; ++i) cpa16(sb + ABUF(buf) + aOff[i], aP[i] + ka);
#pragma unroll
        for (int i = 0; i < 4; ++i) cpa16(sb + BBUF(buf) + bOff[i], bP[i] + kb);
        cp_commit();
    };

    issue(0, 0);

    const uint32_t a_row = (lane & 15), a_kq = (lane >> 4);
    const uint32_t b_kr = (lane & 7) + (lane >> 4) * 8;
    const uint32_t b_nc = wn * 8 + ((lane >> 3) & 1);

    for (int kt = 0; kt < NCH; ++kt) {
        const int buf = kt & 1;
        if (kt + 1 < NCH) { issue(kt + 1, buf ^ 1); cp_wait1(); }
        else cp_wait0();
        __syncthreads();

        const uint32_t aB = sb + ABUF(buf);
        const uint32_t bB = sb + BBUF(buf);

#pragma unroll
        for (int ks = 0; ks < 4; ++ks) {
            uint32_t fA[2][4];
#pragma unroll
            for (int tm = 0; tm < 2; ++tm) {
                uint32_t ao = (wm * 32 + tm * 16 + a_row) * APITCH + (ks * 16 + a_kq * 8) * 2;
                ldsm4(fA[tm], aB + ao);
            }
            const uint32_t kr = ks * 16 + b_kr;
            const uint32_t krl = kr & 7;
#pragma unroll
            for (int nb = 0; nb < 4; ++nb) {
                uint32_t nc = b_nc + nb * 2;
                uint32_t bo = kr * 256 + ((nc ^ krl) << 4);
                uint32_t fB[4];
                ldsm4t(fB, bB + bo);
#pragma unroll
                for (int tm = 0; tm < 2; ++tm) {
                    mmaf16(acc[tm][nb * 2 + 0], fA[tm], fB[0], fB[2]);
                    mmaf16(acc[tm][nb * 2 + 1], fA[tm], fB[1], fB[3]);
                }
            }
        }
        __syncthreads();
    }

    // ---- epilogue ----
    const int gid = lane >> 2, tig = lane & 3;
#pragma unroll
    for (int tm = 0; tm < 2; ++tm) {
        const int r0 = m0 + wm * 32 + tm * 16 + gid;
#pragma unroll
        for (int j = 0; j < 8; ++j) {
            const int col = n0 + wn * 64 + j * 8 + tig * 2;
            if (MODE == 0) {
#pragma unroll
                for (int hh = 0; hh < 2; ++hh) {
                    int row = r0 + hh * 8;
                    if (row >= cnt) continue;
                    float v0 = fmaxf(acc[tm][j][hh * 2 + 0], 0.f);
                    float v1 = fmaxf(acc[tm][j][hh * 2 + 1], 0.f);
                    uint32_t h0 = f2h(v0), h1 = f2h(v1);
                    size_t idx = (size_t)(e * CAPS + row) * 4096 + col;
                    *(uint32_t*)(g_hh + idx) = h0 | (h1 << 16);
                }
            } else {
#pragma unroll
                for (int hh = 0; hh < 2; ++hh) {
                    int row = r0 + hh * 8;
                    int slot = e * cap + row;
                    int tok = g_tok4slot[slot];
                    if (tok >= 0) {
                        float g = g_slotgate[slot];
                        red_add_v2(y + (size_t)tok * 1024 + col,
                                   acc[tm][j][hh * 2 + 0] * g,
                                   acc[tm][j][hh * 2 + 1] * g);
                    }
                }
            }
        }
    }
}

// ---------------- launch ----------------
extern "C" void kernel_launch(void* const* d_in, const int* in_sizes, int n_in,
                              void* d_out, int out_size)
{
    const float* x     = (const float*)d_in[0];
    const int*   mask  = (const int*)d_in[1];
    const float* noise = (const float*)d_in[2];
    const float* Wr    = (const float*)d_in[3];
    const float* W1    = (const float*)d_in[4];
    const float* W2    = (const float*)d_in[5];
    float*       out   = (float*)d_out;

    const int  N = in_sizes[1];                      // 8192
    const int  D = in_sizes[0] / N;                  // 1024
    const int  E = in_sizes[2] / N;                  // 16
    const int  H = (int)((long)in_sizes[4] / ((long)E * D)); // 4096
    const int  cap = (int)((long)N * 5 / (4 * E));   // 640
    const long ytot = (long)N * D;

    cudaFuncSetAttribute((const void*)gemm_kernel<0,1>, cudaFuncAttributeMaxDynamicSharedMemorySize, GSMEM);
    cudaFuncSetAttribute((const void*)gemm_kernel<1,4>, cudaFuncAttributeMaxDynamicSharedMemorySize, GSMEM);
    cudaFuncSetAttribute(rank_kernel, cudaFuncAttributeMaxDynamicSharedMemorySize, 65536);

    ushort_t *xh, *w1h, *w2h;
    cudaGetSymbolAddress((void**)&xh, g_xh);
    cudaGetSymbolAddress((void**)&w1h, g_w1h);
    cudaGetSymbolAddress((void**)&w2h, g_w2h);

    init_kernel<<<(unsigned)((ytot / 4 + 255) / 256), 256>>>(out, ytot);
    pack_kernel<<<2048, 256>>>(x, xh, (long)N * D / 4);
    router_kernel<<<N / 8, 256>>>(x, mask, noise, Wr, N, D);
    loss_reduce_kernel<<<1, 32>>>(out, (long)out_size);
    rank_kernel<<<E, 256, (size_t)N * 8>>>(cap);
    pack_kernel<<<4096, 256>>>(W1, w1h, (long)E * D * H / 4);
    pack_kernel<<<4096, 256>>>(W2, w2h, (long)E * D * H / 4);

    gemm_kernel<0,1><<<E * (H / 128) * 5, 256, GSMEM>>>(x, out, cap);
    gemm_kernel<1,4><<<E * (D / 128) * 5 * 4, 256, GSMEM>>>(W2 ? out : out, out, cap);
}